// round 8
// baseline (speedup 1.0000x reference)
#include <cuda_runtime.h>
#include <cuda_fp16.h>
#include <cstdint>
#include <math.h>

#define PWH 72
#define NTH 512
typedef unsigned long long ull;

struct SmC {
    __half tile[8][34][PWH];        // fp16 padded tile; interior rows 1..32, cols 2..65
    ull sw2[8][32];                 // packed (sw[j], sw[j+4]) pairs, 16B-aligned
    ull Weff2[72];                  // packed (w,w) conv taps
    float excol[2][8][64];
    float colm[8][64];
    float exedge[2][8];
    float excor[2][8][2];
    float exsg[2][8][2];
    float exsg2[2][8][2];
    float rowsum[8][32];
    float sh[8][32];
    float sw[8][64];
    float accp[2][32][64];          // F1 partial sums (ci 0-3 / ci 4-7)
    float w1s[64];
    float w3s[576];
    float b1s[8], b3s[8], gnws[8], gnbs[8];
    float T[8], S2l[8];
    float Aarr[8], Kpart[8];
};

__device__ __forceinline__ float sigf(float v) {
    return 1.0f / (1.0f + __expf(-v));
}

__device__ __forceinline__ ull pk2(float a, float b) {
    ull r;
    asm("mov.b64 %0, {%1, %2};" : "=l"(r) : "f"(a), "f"(b));
    return r;
}
__device__ __forceinline__ void upk2(ull v, float& a, float& b) {
    asm("mov.b64 {%0, %1}, %2;" : "=f"(a), "=f"(b) : "l"(v));
}
__device__ __forceinline__ ull mul2(ull a, ull b) {
    ull d;
    asm("mul.rn.f32x2 %0, %1, %2;" : "=l"(d) : "l"(a), "l"(b));
    return d;
}
__device__ __forceinline__ void fma2(ull& d, ull a, ull b) {
    asm("fma.rn.f32x2 %0, %1, %2, %0;" : "+l"(d) : "l"(a), "l"(b));
}

__device__ __forceinline__ uint32_t s2u(const void* p) {
    uint32_t a;
    asm("{ .reg .u64 t; cvta.to.shared.u64 t, %1; cvt.u32.u64 %0, t; }" : "=r"(a) : "l"(p));
    return a;
}
__device__ __forceinline__ void st_peer(const void* laddr, uint32_t prank, float v) {
    uint32_t la = s2u(laddr);
    uint32_t ra;
    asm volatile("mapa.shared::cluster.u32 %0, %1, %2;" : "=r"(ra) : "r"(la), "r"(prank));
    asm volatile("st.shared::cluster.f32 [%0], %1;" :: "r"(ra), "f"(v) : "memory");
}
__device__ __forceinline__ void st_peer64(const void* laddr, uint32_t prank, ull v) {
    uint32_t la = s2u(laddr);
    uint32_t ra;
    asm volatile("mapa.shared::cluster.u32 %0, %1, %2;" : "=r"(ra) : "r"(la), "r"(prank));
    asm volatile("st.shared::cluster.b64 [%0], %1;" :: "r"(ra), "l"(v) : "memory");
}

#define CLUSTER_SYNC() do { \
    asm volatile("barrier.cluster.arrive.aligned;" ::: "memory"); \
    asm volatile("barrier.cluster.wait.aligned;" ::: "memory"); \
} while (0)

// load 12 consecutive padded halfs (16B-aligned) -> 12 floats
__device__ __forceinline__ void ld12(const __half* p, float* w) {
    uint4 a = *(const uint4*)p;
    uint2 b = *(const uint2*)(p + 8);
    float2 f;
    f = __half22float2(*(__half2*)&a.x); w[0] = f.x;  w[1] = f.y;
    f = __half22float2(*(__half2*)&a.y); w[2] = f.x;  w[3] = f.y;
    f = __half22float2(*(__half2*)&a.z); w[4] = f.x;  w[5] = f.y;
    f = __half22float2(*(__half2*)&a.w); w[6] = f.x;  w[7] = f.y;
    f = __half22float2(*(__half2*)&b.x); w[8] = f.x;  w[9] = f.y;
    f = __half22float2(*(__half2*)&b.y); w[10] = f.x; w[11] = f.y;
}

__global__ void __launch_bounds__(NTH, 2) __cluster_dims__(2, 1, 1)
fused_kernel(const float* __restrict__ x,
             const float* __restrict__ w1, const float* __restrict__ b1,
             const float* __restrict__ w3, const float* __restrict__ b3,
             const float* __restrict__ gnw, const float* __restrict__ gnb,
             float* __restrict__ out)
{
    extern __shared__ char smraw[];
    SmC& s = *reinterpret_cast<SmC*>(smraw);
    const int tid = threadIdx.x;
    uint32_t rank;
    asm("mov.u32 %0, %%cluster_ctarank;" : "=r"(rank));
    const uint32_t prank = 1u - rank;
    const long long g = blockIdx.x >> 1;
    const int rbase = (int)rank * 32;
    const float* src = x + g * 32768;
    float* dst = out + g * 32768;
    const float4* src4 = reinterpret_cast<const float4*>(src);

    // ---- phase A: borders + params + interior load (fp16 STS) + halo row ----
    {
        const __half hz = __float2half(0.f);
        int outer = (rank == 0) ? 0 : 33;
        for (int t = tid; t < 8 * 408; t += NTH) {
            int c = t / 408;
            int u = t % 408;
            if (u < 72) {
                s.tile[c][outer][u] = hz;
            } else {
                int u2 = u - 72;
                int r = u2 >> 3;
                int row = (rank == 0) ? (r + 1) : r;
                int m = u2 & 7;
                int col = (m < 2) ? m : (64 + m);
                s.tile[c][row][col] = hz;
            }
        }
    }
    if (tid < 64) s.w1s[tid] = w1[tid];
    if (tid >= 64 && tid < 72) {
        int c = tid - 64;
        s.b1s[c] = b1[c]; s.b3s[c] = b3[c];
        s.gnws[c] = gnw[c]; s.gnbs[c] = gnb[c];
    }
    for (int t = tid; t < 576; t += NTH) s.w3s[t] = w3[t];

    {
        int i = (tid >> 4) & 31;
        int j4 = (tid & 15) << 2;
        #pragma unroll
        for (int c = 0; c < 8; c++) {
            float4 v = src4[c * 1024 + (rbase + i) * 16 + (j4 >> 2)];
            __half2* p = (__half2*)&s.tile[c][i + 1][j4 + 2];
            p[0] = __floats2half2_rn(v.x, v.y);
            p[1] = __floats2half2_rn(v.z, v.w);
        }
    }
    if (tid < 128) {
        int c = tid >> 4;
        int j4 = (tid & 15) << 2;
        int grow = (rank == 0) ? 32 : 31;
        int prow = (rank == 0) ? 33 : 0;
        float4 v = src4[c * 1024 + grow * 16 + (j4 >> 2)];
        __half2* p = (__half2*)&s.tile[c][prow][j4 + 2];
        p[0] = __floats2half2_rn(v.x, v.y);
        p[1] = __floats2half2_rn(v.z, v.w);
    }
    __syncthreads();

    // ---- phase B (single pass, 512 units): rowsums (HADD2) + colsums (half2) ----
    {
        int t = tid;
        if (t < 256) {
            int c = t >> 5, i = t & 31;
            const uint4* rp = reinterpret_cast<const uint4*>(&s.tile[c][i + 1][0]);
            __half2 a0 = __float2half2_rn(0.f), a1 = a0, a2 = a0, a3 = a0;
            #pragma unroll
            for (int q = 0; q < 9; q++) {
                uint4 u = rp[q];
                a0 = __hadd2(a0, *(__half2*)&u.x);
                a1 = __hadd2(a1, *(__half2*)&u.y);
                a2 = __hadd2(a2, *(__half2*)&u.z);
                a3 = __hadd2(a3, *(__half2*)&u.w);
            }
            __half2 hs = __hadd2(__hadd2(a0, a1), __hadd2(a2, a3));
            float2 f = __half22float2(hs);
            float rsum = f.x + f.y;
            s.rowsum[c][i] = rsum;
            int edgei = (rank == 0) ? 0 : 31;
            if (i == edgei) {
                s.exedge[rank][c] = rsum;
                st_peer(&s.exedge[rank][c], prank, rsum);
            }
        } else {
            int u = t - 256;
            int c = u >> 5, jp = u & 31;     // columns 2jp, 2jp+1
            const __half2* cp = (const __half2*)&s.tile[c][1][2 + 2 * jp];
            __half2 a0 = __float2half2_rn(0.f), a1 = a0;
            #pragma unroll
            for (int r = 0; r < 32; r += 2) {
                a0 = __hadd2(a0, cp[r * (PWH / 2)]);
                a1 = __hadd2(a1, cp[(r + 1) * (PWH / 2)]);
            }
            float2 f = __half22float2(__hadd2(a0, a1));
            *(float2*)&s.excol[rank][c][2 * jp] = f;
            st_peer64(&s.excol[rank][c][2 * jp], prank, pk2(f.x, f.y));
        }
    }
    if (tid < 8) {
        int c = tid;
        float a, b;
        if (rank == 0) { a = __half2float(s.tile[c][1][2]);  b = __half2float(s.tile[c][1][65]); }
        else           { a = __half2float(s.tile[c][32][2]); b = __half2float(s.tile[c][32][65]); }
        s.excor[rank][c][0] = a;
        s.excor[rank][c][1] = b;
        st_peer(&s.excor[rank][c][0], prank, a);
        st_peer(&s.excor[rank][c][1], prank, b);
    }
    CLUSTER_SYNC();

    // ---- phase C (single pass): sh + sw (2 cols (j, j+4) per unit, pack sw2) ----
    {
        const float inv = 1.0f / 64.0f;
        int t = tid;
        if (t < 256) {
            int o = t >> 5, i = t & 31;
            float acc = s.b1s[o];
            #pragma unroll
            for (int c = 0; c < 8; c++) acc += s.w1s[o * 8 + c] * (s.rowsum[c][i] * inv);
            s.sh[o][i] = sigf(acc);
        } else {
            int u = t - 256;
            int o = u >> 5;
            int v = u & 31;
            int b = v >> 2, q = v & 3;
            int j = b * 8 + q;
            int j2 = j + 4;
            float acc = s.b1s[o], acc2 = s.b1s[o];
            #pragma unroll
            for (int c = 0; c < 8; c++) {
                float cma = s.excol[0][c][j]  + s.excol[1][c][j];
                float cmb = s.excol[0][c][j2] + s.excol[1][c][j2];
                if (o == 0) { s.colm[c][j] = cma; s.colm[c][j2] = cmb; }
                float wv = s.w1s[o * 8 + c];
                acc  += wv * (cma * inv);
                acc2 += wv * (cmb * inv);
            }
            float g1 = sigf(acc), g2 = sigf(acc2);
            s.sw[o][j]  = g1;
            s.sw[o][j2] = g2;
            s.sw2[o][(b << 2) + q] = pk2(g1, g2);
        }
    }
    __syncthreads();

    // ---- phase D: gated stats (adjacent half2 pairing) + T/S2l, exchange ----
    {
        int w = tid >> 5;
        int c = w >> 1;
        int half = w & 1;
        int lane = tid & 31;
        float2 swp = *(const float2*)&s.sw[c][2 * lane];
        float s0 = 0.f, s1 = 0.f, q0 = 0.f, q1 = 0.f;
        int ibase = half * 16;
        #pragma unroll 4
        for (int r = 0; r < 16; r++) {
            int i = ibase + r;
            float shi = s.sh[c][i];
            __half2 h = *(const __half2*)&s.tile[c][i + 1][2 + 2 * lane];
            float2 gf = __half22float2(h);
            float v0 = gf.x * (shi * swp.x);
            float v1 = gf.y * (shi * swp.y);
            s0 += v0; s1 += v1;
            q0 += v0 * v0; q1 += v1 * v1;
        }
        float sum = s0 + s1, sq = q0 + q1;
        #pragma unroll
        for (int off = 16; off; off >>= 1) {
            sum += __shfl_xor_sync(0xffffffffu, sum, off);
            sq  += __shfl_xor_sync(0xffffffffu, sq,  off);
        }
        if (lane == 0) {
            s.exsg[rank][c][half] = sum;  s.exsg2[rank][c][half] = sq;
            st_peer(&s.exsg[rank][c][half],  prank, sum);
            st_peer(&s.exsg2[rank][c][half], prank, sq);
        }
    }
    if (tid < 8) {
        int c = tid;
        float a0 = 0.f, a1 = 0.f, a2 = 0.f, a3 = 0.f;
        #pragma unroll
        for (int j = 0; j < 64; j += 4) {
            a0 += s.colm[c][j];     a1 += s.colm[c][j + 1];
            a2 += s.colm[c][j + 2]; a3 += s.colm[c][j + 3];
        }
        s.T[c] = (a0 + a1) + (a2 + a3);
    }
    __syncthreads();
    if (tid < 8) {
        int c = tid;
        float acc = 0.f;
        #pragma unroll
        for (int ci = 0; ci < 8; ci++) {
            float T   = s.T[ci];
            float r0  = s.exedge[0][ci], r63 = s.exedge[1][ci];
            float c0  = s.colm[ci][0],   c63 = s.colm[ci][63];
            float g00 = s.excor[0][ci][0], g0e = s.excor[0][ci][1];
            float ge0 = s.excor[1][ci][0], gee = s.excor[1][ci][1];
            float Sv[9];
            Sv[0] = T - r63 - c63 + gee;
            Sv[1] = T - r63;
            Sv[2] = T - r63 - c0 + ge0;
            Sv[3] = T - c63;
            Sv[4] = T;
            Sv[5] = T - c0;
            Sv[6] = T - r0 - c63 + g0e;
            Sv[7] = T - r0;
            Sv[8] = T - r0 - c0 + g00;
            const float* wp = &s.w3s[c * 72 + ci * 9];
            #pragma unroll
            for (int t = 0; t < 9; t++) acc += wp[t] * Sv[t];
        }
        s.S2l[c] = acc * (1.0f / 4096.0f) + s.b3s[c];
    }
    CLUSTER_SYNC();

    // ---- phase E: redundant softmaxes -> Weff2 (packed) / Aarr / Kpart ----
    if (tid < 80) {
        float mx1 = -1e30f, mx2 = -1e30f;
        #pragma unroll
        for (int k = 0; k < 8; k++) {
            mx1 = fmaxf(mx1, s.gnbs[k]);
            mx2 = fmaxf(mx2, s.S2l[k]);
        }
        float e1[8], e2[8];
        float d1 = 0.f, d2 = 0.f;
        #pragma unroll
        for (int k = 0; k < 8; k++) {
            e1[k] = __expf(s.gnbs[k] - mx1); d1 += e1[k];
            e2[k] = __expf(s.S2l[k] - mx2);  d2 += e2[k];
        }
        if (tid < 72) {
            int ci = tid / 9, tap = tid % 9;
            float acc = 0.f;
            #pragma unroll
            for (int o = 0; o < 8; o++) acc += e1[o] * s.w3s[o * 72 + ci * 9 + tap];
            float v = acc / d1;
            s.Weff2[tid] = pk2(v, v);
        } else {
            int c = tid - 72;
            float m = (s.exsg[0][c][0] + s.exsg[0][c][1]
                     + s.exsg[1][c][0] + s.exsg[1][c][1]) * (1.0f / 4096.0f);
            float q = (s.exsg2[0][c][0] + s.exsg2[0][c][1]
                     + s.exsg2[1][c][0] + s.exsg2[1][c][1]) * (1.0f / 4096.0f);
            float rsg = rsqrtf(q - m * m + 1e-5f);
            float x21 = e2[c] / d2;
            float x11 = e1[c] / d1;
            float gr = s.gnws[c] * rsg;
            s.Aarr[c]  = x21 * gr;
            s.Kpart[c] = x21 * (s.gnbs[c] - gr * m) + x11 * s.b3s[c];
        }
    }
    __syncthreads();

    // ---- F1: packed f32x2 conv + gating, split over ci halves ----
    {
        int half = tid >> 8;
        int unit = tid & 255;
        int i0 = unit >> 3;
        int j0 = (unit & 7) << 3;
        int cibase = half << 2;
        float init = 0.f;
        if (half == 0) {
            init = ((s.Kpart[0] + s.Kpart[1]) + (s.Kpart[2] + s.Kpart[3]))
                 + ((s.Kpart[4] + s.Kpart[5]) + (s.Kpart[6] + s.Kpart[7]));
        }
        ull acc2[4];
        ull init2 = pk2(init, init);
        #pragma unroll
        for (int q = 0; q < 4; q++) acc2[q] = init2;

        #pragma unroll
        for (int cq = 0; cq < 4; cq++) {
            int ci = cibase + cq;
            float coef = s.Aarr[ci] * s.sh[ci][i0];
            ull coef2 = pk2(coef, coef);
            const ulonglong2* swp2 =
                (const ulonglong2*)&s.sw2[ci][(j0 >> 3) << 2];
            ulonglong2 sa = swp2[0], sb = swp2[1];
            ull gp[4];
            gp[0] = mul2(coef2, sa.x);
            gp[1] = mul2(coef2, sa.y);
            gp[2] = mul2(coef2, sb.x);
            gp[3] = mul2(coef2, sb.y);
            const ull* wq = &s.Weff2[ci * 9];
            float w[12];
            ull P[6];

            // top row: taps 0,1,2
            ld12(&s.tile[ci][i0][j0], w);
            #pragma unroll
            for (int k = 0; k < 6; k++) P[k] = pk2(w[k + 1], w[k + 5]);
            {
                ull t0 = wq[0], t1 = wq[1], t2 = wq[2];
                #pragma unroll
                for (int q = 0; q < 4; q++) {
                    fma2(acc2[q], t0, P[q]);
                    fma2(acc2[q], t1, P[q + 1]);
                    fma2(acc2[q], t2, P[q + 2]);
                }
            }
            // mid row: taps 3,4,5 + gating
            ld12(&s.tile[ci][i0 + 1][j0], w);
            #pragma unroll
            for (int k = 0; k < 6; k++) P[k] = pk2(w[k + 1], w[k + 5]);
            {
                ull t0 = wq[3], t1 = wq[4], t2 = wq[5];
                #pragma unroll
                for (int q = 0; q < 4; q++) {
                    fma2(acc2[q], t0, P[q]);
                    fma2(acc2[q], t1, P[q + 1]);
                    fma2(acc2[q], t2, P[q + 2]);
                    fma2(acc2[q], gp[q], P[q + 1]);
                }
            }
            // bottom row: taps 6,7,8
            ld12(&s.tile[ci][i0 + 2][j0], w);
            #pragma unroll
            for (int k = 0; k < 6; k++) P[k] = pk2(w[k + 1], w[k + 5]);
            {
                ull t0 = wq[6], t1 = wq[7], t2 = wq[8];
                #pragma unroll
                for (int q = 0; q < 4; q++) {
                    fma2(acc2[q], t0, P[q]);
                    fma2(acc2[q], t1, P[q + 1]);
                    fma2(acc2[q], t2, P[q + 2]);
                }
            }
        }
        float a[8];
        #pragma unroll
        for (int q = 0; q < 4; q++) upk2(acc2[q], a[q], a[q + 4]);
        *(float4*)&s.accp[half][i0][j0] = make_float4(a[0], a[1], a[2], a[3]);
        *(float4*)&s.accp[half][i0][j0 + 4] = make_float4(a[4], a[5], a[6], a[7]);
    }
    __syncthreads();

    // ---- F2: wt = sigmoid(acc0+acc1); out = gx(fp32 from L2) * wt ----
    {
        int i = (tid >> 4) & 31;
        int j4 = (tid & 15) << 2;
        float4 p0 = *(const float4*)&s.accp[0][i][j4];
        float4 p1 = *(const float4*)&s.accp[1][i][j4];
        float4 wv = make_float4(sigf(p0.x + p1.x), sigf(p0.y + p1.y),
                                sigf(p0.z + p1.z), sigf(p0.w + p1.w));
        #pragma unroll
        for (int c = 0; c < 8; c++) {
            float4 v = src4[c * 1024 + (rbase + i) * 16 + (j4 >> 2)];
            float4 o4 = make_float4(v.x * wv.x, v.y * wv.y, v.z * wv.z, v.w * wv.w);
            *reinterpret_cast<float4*>(&dst[c * 4096 + (rbase + i) * 64 + j4]) = o4;
        }
    }
}

extern "C" void kernel_launch(void* const* d_in, const int* in_sizes, int n_in,
                              void* d_out, int out_size) {
    (void)in_sizes; (void)n_in; (void)out_size;
    const float* x   = (const float*)d_in[0];
    const float* w1  = (const float*)d_in[1];
    const float* b1  = (const float*)d_in[2];
    const float* w3  = (const float*)d_in[3];
    const float* b3  = (const float*)d_in[4];
    const float* gnw = (const float*)d_in[5];
    const float* gnb = (const float*)d_in[6];
    float* out = (float*)d_out;

    size_t smem = sizeof(SmC);
    cudaFuncSetAttribute(fused_kernel, cudaFuncAttributeMaxDynamicSharedMemorySize, (int)smem);
    fused_kernel<<<2048, NTH, smem>>>(x, w1, b1, w3, b3, gnw, gnb, out);
}

// round 9
// speedup vs baseline: 1.0832x; 1.0832x over previous
#include <cuda_runtime.h>
#include <cuda_fp16.h>
#include <cstdint>
#include <math.h>

#define PWH 72
#define NTH 512

struct SmC {
    __half tile[8][34][PWH];   // fp16 padded tile; interior rows 1..32, cols 2..65
    float excol[2][8][64];
    float colm[8][64];
    float exedge[2][8];
    float excor[2][8][2];
    float exsg[2][8][2];
    float exsg2[2][8][2];
    float rowsum[8][32];
    float sh[8][32];
    float sw[8][64];
    float accp[2][32][64];     // F1 partial sums (ci 0-3 / ci 4-7)
    float w1s[64];
    float w3s[576];
    float b1s[8], b3s[8], gnws[8], gnbs[8];
    float T[8], S2l[8];
    float Aarr[8], Kpart[8];
    float Weff[72];
};

__device__ __forceinline__ float sigf(float v) {
    return 1.0f / (1.0f + __expf(-v));
}

__device__ __forceinline__ uint32_t s2u(const void* p) {
    uint32_t a;
    asm("{ .reg .u64 t; cvta.to.shared.u64 t, %1; cvt.u32.u64 %0, t; }" : "=r"(a) : "l"(p));
    return a;
}
__device__ __forceinline__ void st_peer(const void* laddr, uint32_t prank, float v) {
    uint32_t la = s2u(laddr);
    uint32_t ra;
    asm volatile("mapa.shared::cluster.u32 %0, %1, %2;" : "=r"(ra) : "r"(la), "r"(prank));
    asm volatile("st.shared::cluster.f32 [%0], %1;" :: "r"(ra), "f"(v) : "memory");
}
__device__ __forceinline__ void st_peer64(const void* laddr, uint32_t prank, unsigned long long v) {
    uint32_t la = s2u(laddr);
    uint32_t ra;
    asm volatile("mapa.shared::cluster.u32 %0, %1, %2;" : "=r"(ra) : "r"(la), "r"(prank));
    asm volatile("st.shared::cluster.b64 [%0], %1;" :: "r"(ra), "l"(v) : "memory");
}
__device__ __forceinline__ unsigned long long pk2(float a, float b) {
    unsigned long long r;
    asm("mov.b64 %0, {%1, %2};" : "=l"(r) : "f"(a), "f"(b));
    return r;
}

#define CLUSTER_SYNC() do { \
    asm volatile("barrier.cluster.arrive.aligned;" ::: "memory"); \
    asm volatile("barrier.cluster.wait.aligned;" ::: "memory"); \
} while (0)

// load 12 consecutive padded halfs (16B-aligned) -> 12 floats
__device__ __forceinline__ void ld12(const __half* p, float* w) {
    uint4 a = *(const uint4*)p;
    uint2 b = *(const uint2*)(p + 8);
    float2 f;
    f = __half22float2(*(__half2*)&a.x); w[0] = f.x;  w[1] = f.y;
    f = __half22float2(*(__half2*)&a.y); w[2] = f.x;  w[3] = f.y;
    f = __half22float2(*(__half2*)&a.z); w[4] = f.x;  w[5] = f.y;
    f = __half22float2(*(__half2*)&a.w); w[6] = f.x;  w[7] = f.y;
    f = __half22float2(*(__half2*)&b.x); w[8] = f.x;  w[9] = f.y;
    f = __half22float2(*(__half2*)&b.y); w[10] = f.x; w[11] = f.y;
}

__global__ void __launch_bounds__(NTH, 2) __cluster_dims__(2, 1, 1)
fused_kernel(const float* __restrict__ x,
             const float* __restrict__ w1, const float* __restrict__ b1,
             const float* __restrict__ w3, const float* __restrict__ b3,
             const float* __restrict__ gnw, const float* __restrict__ gnb,
             float* __restrict__ out)
{
    extern __shared__ char smraw[];
    SmC& s = *reinterpret_cast<SmC*>(smraw);
    const int tid = threadIdx.x;
    uint32_t rank;
    asm("mov.u32 %0, %%cluster_ctarank;" : "=r"(rank));
    const uint32_t prank = 1u - rank;
    const long long g = blockIdx.x >> 1;
    const int rbase = (int)rank * 32;
    const float* src = x + g * 32768;
    float* dst = out + g * 32768;
    const float4* src4 = reinterpret_cast<const float4*>(src);

    // ---- phase A: borders + params + interior load (fp16 STS) + halo row ----
    {
        const __half hz = __float2half(0.f);
        int outer = (rank == 0) ? 0 : 33;
        for (int t = tid; t < 8 * 408; t += NTH) {
            int c = t / 408;
            int u = t % 408;
            if (u < 72) {
                s.tile[c][outer][u] = hz;
            } else {
                int u2 = u - 72;
                int r = u2 >> 3;
                int row = (rank == 0) ? (r + 1) : r;
                int m = u2 & 7;
                int col = (m < 2) ? m : (64 + m);
                s.tile[c][row][col] = hz;
            }
        }
    }
    if (tid < 64) s.w1s[tid] = w1[tid];
    if (tid >= 64 && tid < 72) {
        int c = tid - 64;
        s.b1s[c] = b1[c]; s.b3s[c] = b3[c];
        s.gnws[c] = gnw[c]; s.gnbs[c] = gnb[c];
    }
    for (int t = tid; t < 576; t += NTH) s.w3s[t] = w3[t];

    {
        int i = (tid >> 4) & 31;
        int j4 = (tid & 15) << 2;
        #pragma unroll
        for (int c = 0; c < 8; c++) {
            float4 v = src4[c * 1024 + (rbase + i) * 16 + (j4 >> 2)];
            __half2* p = (__half2*)&s.tile[c][i + 1][j4 + 2];
            p[0] = __floats2half2_rn(v.x, v.y);
            p[1] = __floats2half2_rn(v.z, v.w);
        }
    }
    if (tid < 128) {
        int c = tid >> 4;
        int j4 = (tid & 15) << 2;
        int grow = (rank == 0) ? 32 : 31;
        int prow = (rank == 0) ? 33 : 0;
        float4 v = src4[c * 1024 + grow * 16 + (j4 >> 2)];
        __half2* p = (__half2*)&s.tile[c][prow][j4 + 2];
        p[0] = __floats2half2_rn(v.x, v.y);
        p[1] = __floats2half2_rn(v.z, v.w);
    }
    __syncthreads();

    // ---- phase B (single pass, 512 units): rowsums (HADD2) + colsums (half2) ----
    {
        int t = tid;
        if (t < 256) {
            int c = t >> 5, i = t & 31;
            const uint4* rp = reinterpret_cast<const uint4*>(&s.tile[c][i + 1][0]);
            __half2 a0 = __float2half2_rn(0.f), a1 = a0, a2 = a0, a3 = a0;
            #pragma unroll
            for (int q = 0; q < 9; q++) {
                uint4 u = rp[q];
                a0 = __hadd2(a0, *(__half2*)&u.x);
                a1 = __hadd2(a1, *(__half2*)&u.y);
                a2 = __hadd2(a2, *(__half2*)&u.z);
                a3 = __hadd2(a3, *(__half2*)&u.w);
            }
            __half2 hs = __hadd2(__hadd2(a0, a1), __hadd2(a2, a3));
            float2 f = __half22float2(hs);
            float rsum = f.x + f.y;
            s.rowsum[c][i] = rsum;
            int edgei = (rank == 0) ? 0 : 31;
            if (i == edgei) {
                s.exedge[rank][c] = rsum;
                st_peer(&s.exedge[rank][c], prank, rsum);
            }
        } else {
            int u = t - 256;
            int c = u >> 5, jp = u & 31;     // columns 2jp, 2jp+1
            const __half2* cp = (const __half2*)&s.tile[c][1][2 + 2 * jp];
            __half2 a0 = __float2half2_rn(0.f), a1 = a0;
            #pragma unroll
            for (int r = 0; r < 32; r += 2) {
                a0 = __hadd2(a0, cp[r * (PWH / 2)]);
                a1 = __hadd2(a1, cp[(r + 1) * (PWH / 2)]);
            }
            float2 f = __half22float2(__hadd2(a0, a1));
            *(float2*)&s.excol[rank][c][2 * jp] = f;
            st_peer64(&s.excol[rank][c][2 * jp], prank, pk2(f.x, f.y));
        }
    }
    if (tid < 8) {
        int c = tid;
        float a, b;
        if (rank == 0) { a = __half2float(s.tile[c][1][2]);  b = __half2float(s.tile[c][1][65]); }
        else           { a = __half2float(s.tile[c][32][2]); b = __half2float(s.tile[c][32][65]); }
        s.excor[rank][c][0] = a;
        s.excor[rank][c][1] = b;
        st_peer(&s.excor[rank][c][0], prank, a);
        st_peer(&s.excor[rank][c][1], prank, b);
    }
    CLUSTER_SYNC();

    // ---- phase C (single pass): sh + sw (2 cols per unit) ----
    {
        const float inv = 1.0f / 64.0f;
        int t = tid;
        if (t < 256) {
            int o = t >> 5, i = t & 31;
            float acc = s.b1s[o];
            #pragma unroll
            for (int c = 0; c < 8; c++) acc += s.w1s[o * 8 + c] * (s.rowsum[c][i] * inv);
            s.sh[o][i] = sigf(acc);
        } else {
            int u = t - 256;
            int o = u >> 5;
            int v = u & 31;
            int j = 2 * v;
            int j2 = j + 1;
            float acc = s.b1s[o], acc2 = s.b1s[o];
            #pragma unroll
            for (int c = 0; c < 8; c++) {
                float cma = s.excol[0][c][j]  + s.excol[1][c][j];
                float cmb = s.excol[0][c][j2] + s.excol[1][c][j2];
                if (o == 0) { s.colm[c][j] = cma; s.colm[c][j2] = cmb; }
                float wv = s.w1s[o * 8 + c];
                acc  += wv * (cma * inv);
                acc2 += wv * (cmb * inv);
            }
            s.sw[o][j]  = sigf(acc);
            s.sw[o][j2] = sigf(acc2);
        }
    }
    __syncthreads();

    // ---- phase D: gated stats (adjacent half2 pairing) + T/S2l, exchange ----
    {
        int w = tid >> 5;
        int c = w >> 1;
        int half = w & 1;
        int lane = tid & 31;
        float2 swp = *(const float2*)&s.sw[c][2 * lane];
        float s0 = 0.f, s1 = 0.f, q0 = 0.f, q1 = 0.f;
        int ibase = half * 16;
        #pragma unroll 4
        for (int r = 0; r < 16; r++) {
            int i = ibase + r;
            float shi = s.sh[c][i];
            __half2 h = *(const __half2*)&s.tile[c][i + 1][2 + 2 * lane];
            float2 gf = __half22float2(h);
            float v0 = gf.x * (shi * swp.x);
            float v1 = gf.y * (shi * swp.y);
            s0 += v0; s1 += v1;
            q0 += v0 * v0; q1 += v1 * v1;
        }
        float sum = s0 + s1, sq = q0 + q1;
        #pragma unroll
        for (int off = 16; off; off >>= 1) {
            sum += __shfl_xor_sync(0xffffffffu, sum, off);
            sq  += __shfl_xor_sync(0xffffffffu, sq,  off);
        }
        if (lane == 0) {
            s.exsg[rank][c][half] = sum;  s.exsg2[rank][c][half] = sq;
            st_peer(&s.exsg[rank][c][half],  prank, sum);
            st_peer(&s.exsg2[rank][c][half], prank, sq);
        }
    }
    if (tid < 8) {
        int c = tid;
        float a0 = 0.f, a1 = 0.f, a2 = 0.f, a3 = 0.f;
        #pragma unroll
        for (int j = 0; j < 64; j += 4) {
            a0 += s.colm[c][j];     a1 += s.colm[c][j + 1];
            a2 += s.colm[c][j + 2]; a3 += s.colm[c][j + 3];
        }
        s.T[c] = (a0 + a1) + (a2 + a3);
    }
    __syncthreads();
    if (tid < 8) {
        int c = tid;
        float acc = 0.f;
        #pragma unroll
        for (int ci = 0; ci < 8; ci++) {
            float T   = s.T[ci];
            float r0  = s.exedge[0][ci], r63 = s.exedge[1][ci];
            float c0  = s.colm[ci][0],   c63 = s.colm[ci][63];
            float g00 = s.excor[0][ci][0], g0e = s.excor[0][ci][1];
            float ge0 = s.excor[1][ci][0], gee = s.excor[1][ci][1];
            float Sv[9];
            Sv[0] = T - r63 - c63 + gee;
            Sv[1] = T - r63;
            Sv[2] = T - r63 - c0 + ge0;
            Sv[3] = T - c63;
            Sv[4] = T;
            Sv[5] = T - c0;
            Sv[6] = T - r0 - c63 + g0e;
            Sv[7] = T - r0;
            Sv[8] = T - r0 - c0 + g00;
            const float* wp = &s.w3s[c * 72 + ci * 9];
            #pragma unroll
            for (int t = 0; t < 9; t++) acc += wp[t] * Sv[t];
        }
        s.S2l[c] = acc * (1.0f / 4096.0f) + s.b3s[c];
    }
    CLUSTER_SYNC();

    // ---- phase E: redundant softmaxes -> Weff / Aarr / Kpart ----
    if (tid < 80) {
        float mx1 = -1e30f, mx2 = -1e30f;
        #pragma unroll
        for (int k = 0; k < 8; k++) {
            mx1 = fmaxf(mx1, s.gnbs[k]);
            mx2 = fmaxf(mx2, s.S2l[k]);
        }
        float e1[8], e2[8];
        float d1 = 0.f, d2 = 0.f;
        #pragma unroll
        for (int k = 0; k < 8; k++) {
            e1[k] = __expf(s.gnbs[k] - mx1); d1 += e1[k];
            e2[k] = __expf(s.S2l[k] - mx2);  d2 += e2[k];
        }
        if (tid < 72) {
            int ci = tid / 9, tap = tid % 9;
            float acc = 0.f;
            #pragma unroll
            for (int o = 0; o < 8; o++) acc += e1[o] * s.w3s[o * 72 + ci * 9 + tap];
            s.Weff[tid] = acc / d1;
        } else {
            int c = tid - 72;
            float m = (s.exsg[0][c][0] + s.exsg[0][c][1]
                     + s.exsg[1][c][0] + s.exsg[1][c][1]) * (1.0f / 4096.0f);
            float q = (s.exsg2[0][c][0] + s.exsg2[0][c][1]
                     + s.exsg2[1][c][0] + s.exsg2[1][c][1]) * (1.0f / 4096.0f);
            float rsg = rsqrtf(q - m * m + 1e-5f);
            float x21 = e2[c] / d2;
            float x11 = e1[c] / d1;
            float gr = s.gnws[c] * rsg;
            s.Aarr[c]  = x21 * gr;
            s.Kpart[c] = x21 * (s.gnbs[c] - gr * m) + x11 * s.b3s[c];
        }
    }
    __syncthreads();

    // ---- F1: scalar fused conv + gated-norm, split over ci halves ----
    {
        int half = tid >> 8;             // 0: ci 0-3, 1: ci 4-7
        int unit = tid & 255;
        int i0 = unit >> 3;              // local output row 0..31
        int j0 = (unit & 7) << 3;        // output cols j0..j0+7
        int cibase = half << 2;
        float acc[8];
        float init = 0.f;
        if (half == 0) {
            init = ((s.Kpart[0] + s.Kpart[1]) + (s.Kpart[2] + s.Kpart[3]))
                 + ((s.Kpart[4] + s.Kpart[5]) + (s.Kpart[6] + s.Kpart[7]));
        }
        #pragma unroll
        for (int p = 0; p < 8; p++) acc[p] = init;

        #pragma unroll
        for (int cq = 0; cq < 4; cq++) {
            int ci = cibase + cq;
            const float* wc = &s.Weff[ci * 9];
            float c0w = wc[0], c1w = wc[1], c2w = wc[2];
            float c3w = wc[3], c4w = wc[4], c5w = wc[5];
            float c6w = wc[6], c7w = wc[7], c8w = wc[8];
            float coef = s.Aarr[ci] * s.sh[ci][i0];
            float4 swa = *(const float4*)&s.sw[ci][j0];
            float4 swb = *(const float4*)&s.sw[ci][j0 + 4];
            float swp[8] = {swa.x, swa.y, swa.z, swa.w, swb.x, swb.y, swb.z, swb.w};
            float w[12];
            ld12(&s.tile[ci][i0][j0], w);
            #pragma unroll
            for (int p = 0; p < 8; p++)
                acc[p] += c0w * w[p + 1] + c1w * w[p + 2] + c2w * w[p + 3];
            ld12(&s.tile[ci][i0 + 1][j0], w);
            #pragma unroll
            for (int p = 0; p < 8; p++)
                acc[p] += c3w * w[p + 1] + c4w * w[p + 2] + c5w * w[p + 3]
                        + coef * swp[p] * w[p + 2];
            ld12(&s.tile[ci][i0 + 2][j0], w);
            #pragma unroll
            for (int p = 0; p < 8; p++)
                acc[p] += c6w * w[p + 1] + c7w * w[p + 2] + c8w * w[p + 3];
        }
        *(float4*)&s.accp[half][i0][j0] =
            make_float4(acc[0], acc[1], acc[2], acc[3]);
        *(float4*)&s.accp[half][i0][j0 + 4] =
            make_float4(acc[4], acc[5], acc[6], acc[7]);
    }
    __syncthreads();

    // ---- F2: wt = sigmoid(acc0+acc1); out = gx(fp32 from L2) * wt ----
    {
        int i = (tid >> 4) & 31;
        int j4 = (tid & 15) << 2;
        float4 p0 = *(const float4*)&s.accp[0][i][j4];
        float4 p1 = *(const float4*)&s.accp[1][i][j4];
        float4 wv = make_float4(sigf(p0.x + p1.x), sigf(p0.y + p1.y),
                                sigf(p0.z + p1.z), sigf(p0.w + p1.w));
        #pragma unroll
        for (int c = 0; c < 8; c++) {
            float4 v = src4[c * 1024 + (rbase + i) * 16 + (j4 >> 2)];
            float4 o4 = make_float4(v.x * wv.x, v.y * wv.y, v.z * wv.z, v.w * wv.w);
            *reinterpret_cast<float4*>(&dst[c * 4096 + (rbase + i) * 64 + j4]) = o4;
        }
    }
}

extern "C" void kernel_launch(void* const* d_in, const int* in_sizes, int n_in,
                              void* d_out, int out_size) {
    (void)in_sizes; (void)n_in; (void)out_size;
    const float* x   = (const float*)d_in[0];
    const float* w1  = (const float*)d_in[1];
    const float* b1  = (const float*)d_in[2];
    const float* w3  = (const float*)d_in[3];
    const float* b3  = (const float*)d_in[4];
    const float* gnw = (const float*)d_in[5];
    const float* gnb = (const float*)d_in[6];
    float* out = (float*)d_out;

    size_t smem = sizeof(SmC);
    cudaFuncSetAttribute(fused_kernel, cudaFuncAttributeMaxDynamicSharedMemorySize, (int)smem);
    fused_kernel<<<2048, NTH, smem>>>(x, w1, b1, w3, b3, gnw, gnb, out);
}